// round 4
// baseline (speedup 1.0000x reference)
#include <cuda_runtime.h>

#define D 128            // DH == DX == 128
#define MAX_M 4096
#define MAX_N 262144

#define PROJ_BLOCKS 256      // 16 rows each -> 4096 rows
#define PROJ_ROWS   16

// Scratch (no allocations allowed): proj matrix + segment offsets
__device__ float g_proj[MAX_M * D];
__device__ int   g_offsets[MAX_M + 1];

// ---------------------------------------------------------------------------
// Kernel A (fused): blocks [0, PROJ_BLOCKS) compute proj = h @ a;
// blocks [PROJ_BLOCKS, ...) compute segment offsets from sorted segment_ids.
// ---------------------------------------------------------------------------
__global__ __launch_bounds__(256) void pre_kernel(const float* __restrict__ h,
                                                  const float* __restrict__ a,
                                                  const int* __restrict__ seg,
                                                  int n, int m) {
    __shared__ float a_sh[64 * D];          // 32 KB (one k-half of a)
    __shared__ float h_sh[PROJ_ROWS * D];   // 8 KB

    int tid = threadIdx.x;

    if (blockIdx.x < PROJ_BLOCKS) {
        // ---------------- proj = h @ a, 16 rows per block ----------------
        int cg = tid & 31;   // 4 cols starting at cg*4
        int rg = tid >> 5;   // 2 rows starting at rg*2
        int rowBase = blockIdx.x * PROJ_ROWS;

        const float4* h4 = (const float4*)h;
        const float4* a4 = (const float4*)a;
        float4* h_sh4 = (float4*)h_sh;
        float4* a_sh4 = (float4*)a_sh;

        for (int idx = tid; idx < PROJ_ROWS * (D / 4); idx += 256)
            h_sh4[idx] = h4[rowBase * (D / 4) + idx];

        float acc[2][4];
#pragma unroll
        for (int r = 0; r < 2; r++)
            acc[r][0] = acc[r][1] = acc[r][2] = acc[r][3] = 0.f;

        for (int half = 0; half < 2; half++) {
            __syncthreads();
            for (int idx = tid; idx < 64 * (D / 4); idx += 256)
                a_sh4[idx] = a4[half * 64 * (D / 4) + idx];
            __syncthreads();

#pragma unroll 8
            for (int k2 = 0; k2 < 64; k2++) {
                float4 av = *(const float4*)&a_sh[k2 * D + cg * 4];
                int k = half * 64 + k2;
#pragma unroll
                for (int r = 0; r < 2; r++) {
                    float hv = h_sh[(rg * 2 + r) * D + k];  // uniform: broadcast
                    acc[r][0] = fmaf(hv, av.x, acc[r][0]);
                    acc[r][1] = fmaf(hv, av.y, acc[r][1]);
                    acc[r][2] = fmaf(hv, av.z, acc[r][2]);
                    acc[r][3] = fmaf(hv, av.w, acc[r][3]);
                }
            }
        }

        float4* p4 = (float4*)g_proj;
#pragma unroll
        for (int r = 0; r < 2; r++) {
            int row = rowBase + rg * 2 + r;
            p4[row * (D / 4) + cg] =
                make_float4(acc[r][0], acc[r][1], acc[r][2], acc[r][3]);
        }
    } else {
        // ---------------- segment offsets (int4 per thread) ----------------
        int t = (blockIdx.x - PROJ_BLOCKS) * 256 + tid;   // ids [4t, 4t+4)
        int base = t * 4;
        if (base >= n) return;
        int4 v = ((const int4*)seg)[t];
        int prev = (base == 0) ? -1 : __ldg(&seg[base - 1]);

        int ids[4] = {v.x, v.y, v.z, v.w};
#pragma unroll
        for (int k = 0; k < 4; k++) {
            int s = ids[k];
            for (int g = prev + 1; g <= s; ++g) g_offsets[g] = base + k;
            prev = s;
        }
        if (base + 4 >= n) {
            for (int g = prev + 1; g <= m; ++g) g_offsets[g] = n;
        }
    }
}

// ---------------------------------------------------------------------------
// Kernel B: TWO WARPS PER GRAPH online-softmax attention.
// Warp pair (2p, 2p+1) splits graph p's contiguous node range into two
// halves; each runs an independent flash accumulator; the pair is merged
// through smem with one block barrier. Lane l owns columns 4l..4l+3.
// ---------------------------------------------------------------------------
__device__ __forceinline__ float warp_dot(float4 v, float4 p) {
    float d = fmaf(v.x, p.x, fmaf(v.y, p.y, fmaf(v.z, p.z, v.w * p.w)));
    d += __shfl_xor_sync(0xffffffffu, d, 16);
    d += __shfl_xor_sync(0xffffffffu, d, 8);
    d += __shfl_xor_sync(0xffffffffu, d, 4);
    d += __shfl_xor_sync(0xffffffffu, d, 2);
    d += __shfl_xor_sync(0xffffffffu, d, 1);
    return d;   // all lanes hold the full dot product
}

__global__ __launch_bounds__(256) void attn_kernel(const float4* __restrict__ x4,
                                                   float* __restrict__ out,
                                                   int m) {
    int lane = threadIdx.x & 31;
    int w    = threadIdx.x >> 5;   // 0..7
    int pp   = w >> 1;             // pair id 0..3
    int half = w & 1;
    int g    = blockIdx.x * 4 + pp;

    __shared__ float  s_m[8];
    __shared__ float  s_z[8];
    __shared__ float4 s_acc[4][32];   // odd warp's accumulator

    bool active = (g < m);
    int s = 0, e = 0;
    if (active) { s = g_offsets[g]; e = g_offsets[g + 1]; }
    int cnt = e - s;
    int h0  = (cnt + 1) >> 1;                 // half0 gets the extra node
    int beg = half ? (s + h0) : s;
    int fin = half ? e : (s + h0);

    const float NEG_INF = -3.402823466e38f;
    float  m_w = NEG_INF;
    float  z_w = 0.f;
    float4 acc = make_float4(0.f, 0.f, 0.f, 0.f);

    float4 p = make_float4(0.f, 0.f, 0.f, 0.f);
    if (active && cnt > 0)
        p = ((const float4*)g_proj)[g * 32 + lane];

    int i = beg;
    // ---- main loop: 4 nodes per iteration (4 independent dot chains) ----
    for (; i + 4 <= fin; i += 4) {
        const float4* b = x4 + i * 32 + lane;
        float4 v0 = b[0];
        float4 v1 = b[32];
        float4 v2 = b[64];
        float4 v3 = b[96];
        float d0 = warp_dot(v0, p);
        float d1 = warp_dot(v1, p);
        float d2 = warp_dot(v2, p);
        float d3 = warp_dot(v3, p);
        float m_new = fmaxf(fmaxf(m_w, fmaxf(d0, d1)), fmaxf(d2, d3));
        float c  = __expf(m_w - m_new);    // 0 on first iteration
        float e0 = __expf(d0 - m_new);
        float e1 = __expf(d1 - m_new);
        float e2 = __expf(d2 - m_new);
        float e3 = __expf(d3 - m_new);
        z_w   = fmaf(z_w, c, (e0 + e1) + (e2 + e3));
        acc.x = fmaf(acc.x, c, fmaf(e0, v0.x, fmaf(e1, v1.x, fmaf(e2, v2.x, e3 * v3.x))));
        acc.y = fmaf(acc.y, c, fmaf(e0, v0.y, fmaf(e1, v1.y, fmaf(e2, v2.y, e3 * v3.y))));
        acc.z = fmaf(acc.z, c, fmaf(e0, v0.z, fmaf(e1, v1.z, fmaf(e2, v2.z, e3 * v3.z))));
        acc.w = fmaf(acc.w, c, fmaf(e0, v0.w, fmaf(e1, v1.w, fmaf(e2, v2.w, e3 * v3.w))));
        m_w = m_new;
    }
    // ---- remainder (up to 3 nodes) ----
    for (; i < fin; ++i) {
        float4 v = x4[i * 32 + lane];
        float d  = warp_dot(v, p);
        float m_new = fmaxf(m_w, d);
        float c = __expf(m_w - m_new);
        float ev = __expf(d - m_new);
        z_w   = fmaf(z_w, c, ev);
        acc.x = fmaf(acc.x, c, ev * v.x);
        acc.y = fmaf(acc.y, c, ev * v.y);
        acc.z = fmaf(acc.z, c, ev * v.z);
        acc.w = fmaf(acc.w, c, ev * v.w);
        m_w = m_new;
    }

    // ---- pair combine ----
    if (lane == 0) { s_m[w] = m_w; s_z[w] = z_w; }
    if (half) s_acc[pp][lane] = acc;
    __syncthreads();

    if (!half && active) {
        float4* out4 = (float4*)out;
        if (cnt <= 0) {
            out4[g * 32 + lane] = make_float4(0.f, 0.f, 0.f, 0.f);
        } else {
            float  m1 = s_m[w + 1];
            float  z1 = s_z[w + 1];
            float4 a1 = s_acc[pp][lane];
            float mg = fmaxf(m_w, m1);           // finite: half0 non-empty
            float f0 = __expf(m_w - mg);
            float f1 = __expf(m1 - mg);          // 0 if half1 empty
            float z  = fmaf(z_w, f0, z1 * f1);
            float inv = 1.f / z;
            out4[g * 32 + lane] = make_float4(
                fmaf(acc.x, f0, a1.x * f1) * inv,
                fmaf(acc.y, f0, a1.y * f1) * inv,
                fmaf(acc.z, f0, a1.z * f1) * inv,
                fmaf(acc.w, f0, a1.w * f1) * inv);
        }
    }
}

// ---------------------------------------------------------------------------
// Launch: inputs per metadata order: h (M*128 f32), x (N*128 f32),
// a (128*128 f32), segment_ids (N int32). Output: M*128 f32.
// ---------------------------------------------------------------------------
extern "C" void kernel_launch(void* const* d_in, const int* in_sizes, int n_in,
                              void* d_out, int out_size) {
    const float* h   = (const float*)d_in[0];
    const float* x   = (const float*)d_in[1];
    const float* a   = (const float*)d_in[2];
    const int*   seg = (const int*)d_in[3];
    float* out = (float*)d_out;

    int m = in_sizes[0] / D;   // 4096
    int n = in_sizes[3];       // 262144

    int n4 = (n + 3) / 4;
    int off_blocks = (n4 + 255) / 256;
    pre_kernel<<<PROJ_BLOCKS + off_blocks, 256>>>(h, a, seg, n, m);
    attn_kernel<<<(m + 3) / 4, 256>>>((const float4*)x, out, m);
}

// round 5
// speedup vs baseline: 1.0522x; 1.0522x over previous
#include <cuda_runtime.h>
#include <cstdint>

#define D 128            // DH == DX == 128
#define MAX_M 4096
#define MAX_N 262144

#define PROJ_BLOCKS 256      // 16 rows each -> 4096 rows
#define PROJ_ROWS   16

#define CHUNK  8             // nodes per bulk copy (8 * 512B = 4KB)
#define STAGES 2

// Scratch (no allocations allowed): proj matrix + segment offsets
__device__ float g_proj[MAX_M * D];
__device__ int   g_offsets[MAX_M + 1];

// ---------------------------------------------------------------------------
// PTX helpers: mbarrier + cp.async.bulk (async-proxy global->shared stream)
// ---------------------------------------------------------------------------
__device__ __forceinline__ uint32_t smem_u32(const void* p) {
    return (uint32_t)__cvta_generic_to_shared(p);
}
__device__ __forceinline__ void mbar_init(uint32_t bar, uint32_t cnt) {
    asm volatile("mbarrier.init.shared.b64 [%0], %1;" :: "r"(bar), "r"(cnt) : "memory");
}
__device__ __forceinline__ void mbar_expect(uint32_t bar, uint32_t bytes) {
    asm volatile("mbarrier.arrive.expect_tx.shared.b64 _, [%0], %1;"
                 :: "r"(bar), "r"(bytes) : "memory");
}
__device__ __forceinline__ void bulk_ld(uint32_t dst, const void* src,
                                        uint32_t bytes, uint32_t bar) {
    asm volatile(
        "cp.async.bulk.shared::cta.global.mbarrier::complete_tx::bytes [%0], [%1], %2, [%3];"
        :: "r"(dst), "l"(src), "r"(bytes), "r"(bar) : "memory");
}
__device__ __forceinline__ void mbar_wait(uint32_t bar, uint32_t phase) {
    uint32_t done;
    asm volatile(
        "{\n\t.reg .pred p;\n\t"
        "mbarrier.try_wait.parity.acquire.cta.shared::cta.b64 p, [%1], %2;\n\t"
        "selp.b32 %0, 1, 0, p;\n\t}"
        : "=r"(done) : "r"(bar), "r"(phase) : "memory");
    if (!done) {
        asm volatile(
            "{\n\t.reg .pred P1;\n\t"
            "WAIT_LOOP_%=:\n\t"
            "mbarrier.try_wait.parity.acquire.cta.shared::cta.b64 P1, [%0], %1, 0x989680;\n\t"
            "@P1 bra.uni WAIT_DONE_%=;\n\t"
            "bra.uni WAIT_LOOP_%=;\n\t"
            "WAIT_DONE_%=:\n\t}"
            :: "r"(bar), "r"(phase) : "memory");
    }
}

// ---------------------------------------------------------------------------
// Kernel A (fused): blocks [0, PROJ_BLOCKS) compute proj = h @ a;
// blocks [PROJ_BLOCKS, ...) compute segment offsets from sorted segment_ids.
// ---------------------------------------------------------------------------
__global__ __launch_bounds__(256) void pre_kernel(const float* __restrict__ h,
                                                  const float* __restrict__ a,
                                                  const int* __restrict__ seg,
                                                  int n, int m) {
    __shared__ float a_sh[64 * D];          // 32 KB (one k-half of a)
    __shared__ float h_sh[PROJ_ROWS * D];   // 8 KB

    int tid = threadIdx.x;

    if (blockIdx.x < PROJ_BLOCKS) {
        int cg = tid & 31;
        int rg = tid >> 5;
        int rowBase = blockIdx.x * PROJ_ROWS;

        const float4* h4 = (const float4*)h;
        const float4* a4 = (const float4*)a;
        float4* h_sh4 = (float4*)h_sh;
        float4* a_sh4 = (float4*)a_sh;

        for (int idx = tid; idx < PROJ_ROWS * (D / 4); idx += 256)
            h_sh4[idx] = h4[rowBase * (D / 4) + idx];

        float acc[2][4];
#pragma unroll
        for (int r = 0; r < 2; r++)
            acc[r][0] = acc[r][1] = acc[r][2] = acc[r][3] = 0.f;

        for (int half = 0; half < 2; half++) {
            __syncthreads();
            for (int idx = tid; idx < 64 * (D / 4); idx += 256)
                a_sh4[idx] = a4[half * 64 * (D / 4) + idx];
            __syncthreads();

#pragma unroll 8
            for (int k2 = 0; k2 < 64; k2++) {
                float4 av = *(const float4*)&a_sh[k2 * D + cg * 4];
                int k = half * 64 + k2;
#pragma unroll
                for (int r = 0; r < 2; r++) {
                    float hv = h_sh[(rg * 2 + r) * D + k];
                    acc[r][0] = fmaf(hv, av.x, acc[r][0]);
                    acc[r][1] = fmaf(hv, av.y, acc[r][1]);
                    acc[r][2] = fmaf(hv, av.z, acc[r][2]);
                    acc[r][3] = fmaf(hv, av.w, acc[r][3]);
                }
            }
        }

        float4* p4 = (float4*)g_proj;
#pragma unroll
        for (int r = 0; r < 2; r++) {
            int row = rowBase + rg * 2 + r;
            p4[row * (D / 4) + cg] =
                make_float4(acc[r][0], acc[r][1], acc[r][2], acc[r][3]);
        }
    } else {
        int t = (blockIdx.x - PROJ_BLOCKS) * 256 + tid;
        int base = t * 4;
        if (base >= n) return;
        int4 v = ((const int4*)seg)[t];
        int prev = (base == 0) ? -1 : __ldg(&seg[base - 1]);

        int ids[4] = {v.x, v.y, v.z, v.w};
#pragma unroll
        for (int k = 0; k < 4; k++) {
            int s = ids[k];
            for (int g = prev + 1; g <= s; ++g) g_offsets[g] = base + k;
            prev = s;
        }
        if (base + 4 >= n) {
            for (int g = prev + 1; g <= m; ++g) g_offsets[g] = n;
        }
    }
}

// ---------------------------------------------------------------------------
// Flash helpers
// ---------------------------------------------------------------------------
__device__ __forceinline__ float warp_dot(float4 v, float4 p) {
    float d = fmaf(v.x, p.x, fmaf(v.y, p.y, fmaf(v.z, p.z, v.w * p.w)));
    d += __shfl_xor_sync(0xffffffffu, d, 16);
    d += __shfl_xor_sync(0xffffffffu, d, 8);
    d += __shfl_xor_sync(0xffffffffu, d, 4);
    d += __shfl_xor_sync(0xffffffffu, d, 2);
    d += __shfl_xor_sync(0xffffffffu, d, 1);
    return d;
}

// 4-node flash update; nodes at b[0], b[32], b[64], b[96] (float4 units)
__device__ __forceinline__ void flash4(const float4* __restrict__ b, float4 p,
                                       float& m_w, float& z_w, float4& acc) {
    float4 v0 = b[0];
    float4 v1 = b[32];
    float4 v2 = b[64];
    float4 v3 = b[96];
    float d0 = warp_dot(v0, p);
    float d1 = warp_dot(v1, p);
    float d2 = warp_dot(v2, p);
    float d3 = warp_dot(v3, p);
    float m_new = fmaxf(fmaxf(m_w, fmaxf(d0, d1)), fmaxf(d2, d3));
    float c  = __expf(m_w - m_new);
    float e0 = __expf(d0 - m_new);
    float e1 = __expf(d1 - m_new);
    float e2 = __expf(d2 - m_new);
    float e3 = __expf(d3 - m_new);
    z_w   = fmaf(z_w, c, (e0 + e1) + (e2 + e3));
    acc.x = fmaf(acc.x, c, fmaf(e0, v0.x, fmaf(e1, v1.x, fmaf(e2, v2.x, e3 * v3.x))));
    acc.y = fmaf(acc.y, c, fmaf(e0, v0.y, fmaf(e1, v1.y, fmaf(e2, v2.y, e3 * v3.y))));
    acc.z = fmaf(acc.z, c, fmaf(e0, v0.z, fmaf(e1, v1.z, fmaf(e2, v2.z, e3 * v3.z))));
    acc.w = fmaf(acc.w, c, fmaf(e0, v0.w, fmaf(e1, v1.w, fmaf(e2, v2.w, e3 * v3.w))));
    m_w = m_new;
}

__device__ __forceinline__ void flash1(float4 v, float4 p,
                                       float& m_w, float& z_w, float4& acc) {
    float d  = warp_dot(v, p);
    float m_new = fmaxf(m_w, d);
    float c = __expf(m_w - m_new);
    float e = __expf(d - m_new);
    z_w   = fmaf(z_w, c, e);
    acc.x = fmaf(acc.x, c, e * v.x);
    acc.y = fmaf(acc.y, c, e * v.y);
    acc.z = fmaf(acc.z, c, e * v.z);
    acc.w = fmaf(acc.w, c, e * v.w);
    m_w = m_new;
}

// ---------------------------------------------------------------------------
// Kernel B: TWO WARPS PER GRAPH, bulk-async pipelined online softmax.
// 128-thread blocks; warps (2p, 2p+1) split graph p's contiguous node range.
// Each warp streams its range in 8-node (4KB) chunks via cp.async.bulk into a
// 2-stage smem ring (mbarrier complete_tx), computing chunk c while chunk c+1
// is in flight. Remainder (<8 nodes) via direct LDG. Pair merged through smem.
// ---------------------------------------------------------------------------
__global__ __launch_bounds__(128) void attn_kernel(const float* __restrict__ x,
                                                   float* __restrict__ out,
                                                   int m) {
    __shared__ float4   s_buf[4][STAGES][CHUNK * 32];  // 32 KB
    __shared__ uint64_t s_bar[4][STAGES];
    __shared__ float    s_m[4];
    __shared__ float    s_z[4];
    __shared__ float4   s_accs[2][32];

    int tid  = threadIdx.x;
    int lane = tid & 31;
    int w    = tid >> 5;    // 0..3
    int pp   = w >> 1;      // pair 0..1
    int half = w & 1;
    int g    = blockIdx.x * 2 + pp;

    if (lane == 0) {
        mbar_init(smem_u32(&s_bar[w][0]), 1);
        mbar_init(smem_u32(&s_bar[w][1]), 1);
    }
    __syncthreads();

    bool active = (g < m);
    int s0 = 0, e0 = 0;
    if (active) { s0 = g_offsets[g]; e0 = g_offsets[g + 1]; }
    int cnt = e0 - s0;
    int h0  = (cnt + 1) >> 1;
    int beg = half ? (s0 + h0) : s0;
    int fin = half ? e0 : (s0 + h0);
    int len = fin - beg;
    int nfull = len >> 3;            // full CHUNK-node chunks

    const float4* x4 = (const float4*)x;

    float4 p = make_float4(0.f, 0.f, 0.f, 0.f);
    if (active && cnt > 0)
        p = ((const float4*)g_proj)[g * 32 + lane];

    // ---- prologue: fill the pipeline ----
    if (lane == 0) {
        int npre = nfull < STAGES ? nfull : STAGES;
        for (int k = 0; k < npre; k++) {
            uint32_t bar = smem_u32(&s_bar[w][k]);
            mbar_expect(bar, CHUNK * 512u);
            bulk_ld(smem_u32(&s_buf[w][k][0]),
                    x4 + (size_t)(beg + k * CHUNK) * 32, CHUNK * 512u, bar);
        }
    }

    const float NEG_INF = -3.402823466e38f;
    float  m_w = NEG_INF;
    float  z_w = 0.f;
    float4 acc = make_float4(0.f, 0.f, 0.f, 0.f);

    // ---- main pipelined loop ----
    for (int c = 0; c < nfull; c++) {
        int st = c & 1;
        mbar_wait(smem_u32(&s_bar[w][st]), (c >> 1) & 1);
        const float4* b = &s_buf[w][st][lane];
        flash4(b,       p, m_w, z_w, acc);   // nodes 0..3
        flash4(b + 128, p, m_w, z_w, acc);   // nodes 4..7
        if (c + 2 < nfull && lane == 0) {
            uint32_t bar = smem_u32(&s_bar[w][st]);
            mbar_expect(bar, CHUNK * 512u);
            bulk_ld(smem_u32(&s_buf[w][st][0]),
                    x4 + (size_t)(beg + (c + 2) * CHUNK) * 32, CHUNK * 512u, bar);
        }
    }

    // ---- remainder nodes (<CHUNK) via direct LDG ----
    for (int i = beg + nfull * CHUNK; i < fin; ++i)
        flash1(x4[(size_t)i * 32 + lane], p, m_w, z_w, acc);

    // ---- pair combine ----
    if (lane == 0) { s_m[w] = m_w; s_z[w] = z_w; }
    if (half) s_accs[pp][lane] = acc;
    __syncthreads();

    if (!half && active) {
        float4* out4 = (float4*)out;
        if (cnt <= 0) {
            out4[g * 32 + lane] = make_float4(0.f, 0.f, 0.f, 0.f);
        } else {
            float  m1 = s_m[w + 1];
            float  z1 = s_z[w + 1];
            float4 a1 = s_accs[pp][lane];
            float mg = fmaxf(m_w, m1);       // finite: half0 non-empty
            float f0 = __expf(m_w - mg);
            float f1 = __expf(m1 - mg);      // 0 if half1 empty
            float z  = fmaf(z_w, f0, z1 * f1);
            float inv = 1.f / z;
            out4[g * 32 + lane] = make_float4(
                fmaf(acc.x, f0, a1.x * f1) * inv,
                fmaf(acc.y, f0, a1.y * f1) * inv,
                fmaf(acc.z, f0, a1.z * f1) * inv,
                fmaf(acc.w, f0, a1.w * f1) * inv);
        }
    }
}

// ---------------------------------------------------------------------------
// Launch: inputs per metadata order: h (M*128 f32), x (N*128 f32),
// a (128*128 f32), segment_ids (N int32). Output: M*128 f32.
// ---------------------------------------------------------------------------
extern "C" void kernel_launch(void* const* d_in, const int* in_sizes, int n_in,
                              void* d_out, int out_size) {
    const float* h   = (const float*)d_in[0];
    const float* x   = (const float*)d_in[1];
    const float* a   = (const float*)d_in[2];
    const int*   seg = (const int*)d_in[3];
    float* out = (float*)d_out;

    int m = in_sizes[0] / D;   // 4096
    int n = in_sizes[3];       // 262144

    int n4 = (n + 3) / 4;
    int off_blocks = (n4 + 255) / 256;
    pre_kernel<<<PROJ_BLOCKS + off_blocks, 256>>>(h, a, seg, n, m);
    attn_kernel<<<(m + 1) / 2, 128>>>(x, out, m);
}